// round 2
// baseline (speedup 1.0000x reference)
#include <cuda_runtime.h>
#include <math.h>

#define HID 1024
#define EMB 1024
#define MAXLEN 4096
#define VOCAB 50257
#define NPART 32   // ctx partial blocks

// ---------------- device scratch ----------------
__device__ float g_hnew[HID];
__device__ float g_scores[MAXLEN];
__device__ float g_sm_m;      // softmax max
__device__ float g_sm_invl;   // 1/sum(exp)
__device__ float g_ctx_part[NPART * HID];
__device__ float g_ctx[HID];
__device__ float g_hid[HID];
__device__ float g_lse_m[256];
__device__ float g_lse_l[256];

__device__ __forceinline__ float warp_sum(float v) {
#pragma unroll
    for (int o = 16; o; o >>= 1) v += __shfl_down_sync(0xffffffffu, v, o);
    return v;
}

__device__ __forceinline__ float sigmoidf(float x) { return 1.f / (1.f + expf(-x)); }

// ---------------- K1: gates GEMV + LSTM pointwise ----------------
__global__ void k1_lstm(const float* __restrict__ W_ih, const float* __restrict__ W_hh,
                        const float* __restrict__ b_ih, const float* __restrict__ b_hh,
                        const float* __restrict__ x, const float* __restrict__ h,
                        const float* __restrict__ c, float* __restrict__ out_tail) {
    __shared__ __align__(16) float sx[EMB];
    __shared__ __align__(16) float sh[HID];
    for (int k = threadIdx.x; k < EMB; k += blockDim.x) sx[k] = x[k];
    for (int k = threadIdx.x; k < HID; k += blockDim.x) sh[k] = h[k];
    __syncthreads();

    int j = (blockIdx.x * blockDim.x + threadIdx.x) >> 5;
    int lane = threadIdx.x & 31;
    if (j >= HID) return;

    const float4* x4 = (const float4*)sx;
    const float4* h4 = (const float4*)sh;
    float acc[4];
#pragma unroll
    for (int g = 0; g < 4; g++) {
        const float4* rW = (const float4*)(W_ih + (size_t)(g * HID + j) * EMB);
        const float4* rU = (const float4*)(W_hh + (size_t)(g * HID + j) * HID);
        float a = 0.f;
#pragma unroll
        for (int k = lane; k < EMB / 4; k += 32) {
            float4 w = rW[k], xv = x4[k];
            a += w.x * xv.x + w.y * xv.y + w.z * xv.z + w.w * xv.w;
            float4 u = rU[k], hv = h4[k];
            a += u.x * hv.x + u.y * hv.y + u.z * hv.z + u.w * hv.w;
        }
        acc[g] = warp_sum(a);
    }
    if (lane == 0) {
        float gi = acc[0] + b_ih[j]           + b_hh[j];
        float gf = acc[1] + b_ih[HID + j]     + b_hh[HID + j];
        float gg = acc[2] + b_ih[2 * HID + j] + b_hh[2 * HID + j];
        float go = acc[3] + b_ih[3 * HID + j] + b_hh[3 * HID + j];
        float ig = sigmoidf(gi);
        float fg = sigmoidf(gf);
        float gt = tanhf(gg);
        float og = sigmoidf(go);
        float cn = fg * c[j] + ig * gt;
        float hn = og * tanhf(cn);
        g_hnew[j] = hn;
        out_tail[j] = hn;          // h_new
        out_tail[HID + j] = cn;    // c_new
    }
}

// ---------------- K2: scores[t] = dot(A[t,:], h_new) ----------------
__global__ void k2_scores(const float* __restrict__ A) {
    __shared__ __align__(16) float sh[HID];
    for (int k = threadIdx.x; k < HID; k += blockDim.x) sh[k] = g_hnew[k];
    __syncthreads();

    int t = (blockIdx.x * blockDim.x + threadIdx.x) >> 5;
    int lane = threadIdx.x & 31;
    if (t >= MAXLEN) return;

    const float4* r = (const float4*)(A + (size_t)t * HID);
    const float4* h4 = (const float4*)sh;
    float a = 0.f;
#pragma unroll
    for (int k = lane; k < HID / 4; k += 32) {
        float4 v = r[k], hv = h4[k];
        a += v.x * hv.x + v.y * hv.y + v.z * hv.z + v.w * hv.w;
    }
    a = warp_sum(a);
    if (lane == 0) g_scores[t] = a;
}

// ---------------- K2b: softmax stats over 4096 scores (single block) ----------------
__global__ void k2b_stats() {
    __shared__ float red[1024];
    int tid = threadIdx.x;
    float m = -INFINITY;
#pragma unroll
    for (int t = tid; t < MAXLEN; t += 1024) m = fmaxf(m, g_scores[t]);
    red[tid] = m;
    __syncthreads();
    for (int s = 512; s > 0; s >>= 1) {
        if (tid < s) red[tid] = fmaxf(red[tid], red[tid + s]);
        __syncthreads();
    }
    m = red[0];
    __syncthreads();
    float l = 0.f;
#pragma unroll
    for (int t = tid; t < MAXLEN; t += 1024) l += expf(g_scores[t] - m);
    red[tid] = l;
    __syncthreads();
    for (int s = 512; s > 0; s >>= 1) {
        if (tid < s) red[tid] += red[tid + s];
        __syncthreads();
    }
    if (tid == 0) {
        g_sm_m = m;
        g_sm_invl = 1.f / red[0];
    }
}

// ---------------- K3: ctx partials, 32 blocks x 128 timesteps each ----------------
__global__ void k3_ctx_part(const float* __restrict__ A) {
    __shared__ float w_s[128];
    int tid = threadIdx.x;  // 512
    int t0 = blockIdx.x * 128;
    if (tid < 128) w_s[tid] = expf(g_scores[t0 + tid] - g_sm_m) * g_sm_invl;
    __syncthreads();

    float a0 = 0.f, a1 = 0.f;
#pragma unroll 4
    for (int t = 0; t < 128; t++) {
        const float* row = A + (size_t)(t0 + t) * HID;
        float w = w_s[t];
        a0 += row[tid] * w;
        a1 += row[tid + 512] * w;
    }
    g_ctx_part[blockIdx.x * HID + tid] = a0;
    g_ctx_part[blockIdx.x * HID + tid + 512] = a1;
}

// ---------------- K3b: reduce 32 partials, coalesced + fully unrolled ----------------
__global__ void k3b_ctx_reduce() {
    int d = blockIdx.x * blockDim.x + threadIdx.x;  // 1024 threads total
    float s = 0.f;
#pragma unroll
    for (int b = 0; b < NPART; b++) s += g_ctx_part[b * HID + d];
    g_ctx[d] = s;
}

// ---------------- K4: fc1 GEMV ----------------
__global__ void k4_fc1(const float* __restrict__ fc1_w, const float* __restrict__ fc1_b) {
    __shared__ __align__(16) float sc[2 * HID];
    for (int k = threadIdx.x; k < HID; k += blockDim.x) {
        sc[k] = g_ctx[k];
        sc[HID + k] = g_hnew[k];
    }
    __syncthreads();

    int i = (blockIdx.x * blockDim.x + threadIdx.x) >> 5;
    int lane = threadIdx.x & 31;
    if (i >= HID) return;

    const float4* r = (const float4*)(fc1_w + (size_t)i * 2 * HID);
    const float4* c4 = (const float4*)sc;
    float a = 0.f;
#pragma unroll
    for (int k = lane; k < (2 * HID) / 4; k += 32) {
        float4 v = r[k], cv = c4[k];
        a += v.x * cv.x + v.y * cv.y + v.z * cv.z + v.w * cv.w;
    }
    a = warp_sum(a);
    if (lane == 0) g_hid[i] = a + fc1_b[i];
}

// ---------------- K5: fc2 GEMV -> logits ----------------
__global__ void k5_fc2(const float* __restrict__ fc2_w, const float* __restrict__ fc2_b,
                       float* __restrict__ out) {
    __shared__ __align__(16) float shd[HID];
    for (int k = threadIdx.x; k < HID; k += blockDim.x) shd[k] = g_hid[k];
    __syncthreads();

    int i = (blockIdx.x * blockDim.x + threadIdx.x) >> 5;
    if (i >= VOCAB) return;
    int lane = threadIdx.x & 31;

    const float4* r = (const float4*)(fc2_w + (size_t)i * HID);
    const float4* h4 = (const float4*)shd;
    float a = 0.f;
#pragma unroll
    for (int k = lane; k < HID / 4; k += 32) {
        float4 v = r[k], hv = h4[k];
        a += v.x * hv.x + v.y * hv.y + v.z * hv.z + v.w * hv.w;
    }
    a = warp_sum(a);
    if (lane == 0) out[i] = a + fc2_b[i];
}

// ---------------- K6: lse partials ----------------
__global__ void k6_lse_part(const float* __restrict__ out) {
    __shared__ float sm[256];
    __shared__ float sl[256];
    int idx = blockIdx.x * blockDim.x + threadIdx.x;
    float m = -INFINITY, l = 0.f;
    if (idx < VOCAB) { m = out[idx]; l = 1.f; }
    sm[threadIdx.x] = m;
    sl[threadIdx.x] = l;
    __syncthreads();
    for (int s = 128; s > 0; s >>= 1) {
        if (threadIdx.x < s) {
            float m1 = sm[threadIdx.x], l1 = sl[threadIdx.x];
            float m2 = sm[threadIdx.x + s], l2 = sl[threadIdx.x + s];
            float mm = fmaxf(m1, m2);
            float ll = (l1 > 0.f ? l1 * expf(m1 - mm) : 0.f) +
                       (l2 > 0.f ? l2 * expf(m2 - mm) : 0.f);
            sm[threadIdx.x] = mm;
            sl[threadIdx.x] = ll;
        }
        __syncthreads();
    }
    if (threadIdx.x == 0) {
        g_lse_m[blockIdx.x] = sm[0];
        g_lse_l[blockIdx.x] = sl[0];
    }
}

// ---------------- K7: combine + subtract in place ----------------
__global__ void k7_final(float* __restrict__ out) {
    __shared__ float sm[256];
    __shared__ float sl[256];
    int tid = threadIdx.x;
    sm[tid] = g_lse_m[tid];
    sl[tid] = g_lse_l[tid];
    __syncthreads();
    for (int s = 128; s > 0; s >>= 1) {
        if (tid < s) {
            float m1 = sm[tid], l1 = sl[tid];
            float m2 = sm[tid + s], l2 = sl[tid + s];
            float mm = fmaxf(m1, m2);
            float ll = (l1 > 0.f ? l1 * expf(m1 - mm) : 0.f) +
                       (l2 > 0.f ? l2 * expf(m2 - mm) : 0.f);
            sm[tid] = mm;
            sl[tid] = ll;
        }
        __syncthreads();
    }
    float lse = sm[0] + logf(sl[0]);
    int i = blockIdx.x * 256 + tid;
    if (i < VOCAB) out[i] -= lse;
}

// ---------------- launch ----------------
extern "C" void kernel_launch(void* const* d_in, const int* in_sizes, int n_in,
                              void* d_out, int out_size) {
    const float* attn  = (const float*)d_in[0];
    const float* x     = (const float*)d_in[1];
    const float* h     = (const float*)d_in[2];
    const float* c     = (const float*)d_in[3];
    const float* W_ih  = (const float*)d_in[4];
    const float* W_hh  = (const float*)d_in[5];
    const float* b_ih  = (const float*)d_in[6];
    const float* b_hh  = (const float*)d_in[7];
    const float* fc1_w = (const float*)d_in[8];
    const float* fc1_b = (const float*)d_in[9];
    const float* fc2_w = (const float*)d_in[10];
    const float* fc2_b = (const float*)d_in[11];
    float* out = (float*)d_out;

    k1_lstm<<<256, 128>>>(W_ih, W_hh, b_ih, b_hh, x, h, c, out + VOCAB);
    k2_scores<<<512, 256>>>(attn);
    k2b_stats<<<1, 1024>>>();
    k3_ctx_part<<<NPART, 512>>>(attn);
    k3b_ctx_reduce<<<4, 256>>>();
    k4_fc1<<<128, 256>>>(fc1_w, fc1_b);
    k5_fc2<<<(VOCAB + 7) / 8, 256>>>(fc2_w, fc2_b, out);
    k6_lse_part<<<256, 256>>>(out);
    k7_final<<<(VOCAB + 255) / 256, 256>>>(out);
}

// round 3
// speedup vs baseline: 1.0880x; 1.0880x over previous
#include <cuda_runtime.h>
#include <math.h>

#define HID 1024
#define EMB 1024
#define MAXLEN 4096
#define VOCAB 50257
#define NPART 128   // ctx partial blocks

// ---------------- device scratch ----------------
__device__ float g_hnew[HID];
__device__ float g_scores[MAXLEN];
__device__ float g_ctx_part[NPART * HID];
__device__ float g_ctx[HID];
__device__ float g_hid[HID];
__device__ float g_lse_m[256];
__device__ float g_lse_l[256];

__device__ __forceinline__ float warp_sum(float v) {
#pragma unroll
    for (int o = 16; o; o >>= 1) v += __shfl_down_sync(0xffffffffu, v, o);
    return v;
}
__device__ __forceinline__ float warp_max(float v) {
#pragma unroll
    for (int o = 16; o; o >>= 1) v = fmaxf(v, __shfl_down_sync(0xffffffffu, v, o));
    return v;
}

__device__ __forceinline__ float sigmoidf(float x) { return 1.f / (1.f + expf(-x)); }

// ---------------- K1: gates GEMV + LSTM pointwise ----------------
__global__ void k1_lstm(const float* __restrict__ W_ih, const float* __restrict__ W_hh,
                        const float* __restrict__ b_ih, const float* __restrict__ b_hh,
                        const float* __restrict__ x, const float* __restrict__ h,
                        const float* __restrict__ c, float* __restrict__ out_tail) {
    __shared__ __align__(16) float sx[EMB];
    __shared__ __align__(16) float sh[HID];
    for (int k = threadIdx.x; k < EMB; k += blockDim.x) sx[k] = x[k];
    for (int k = threadIdx.x; k < HID; k += blockDim.x) sh[k] = h[k];
    __syncthreads();

    int j = (blockIdx.x * blockDim.x + threadIdx.x) >> 5;
    int lane = threadIdx.x & 31;
    if (j >= HID) return;

    const float4* x4 = (const float4*)sx;
    const float4* h4 = (const float4*)sh;
    float acc[4];
#pragma unroll
    for (int g = 0; g < 4; g++) {
        const float4* rW = (const float4*)(W_ih + (size_t)(g * HID + j) * EMB);
        const float4* rU = (const float4*)(W_hh + (size_t)(g * HID + j) * HID);
        float a = 0.f;
#pragma unroll
        for (int k = lane; k < EMB / 4; k += 32) {
            float4 w = rW[k], xv = x4[k];
            a += w.x * xv.x + w.y * xv.y + w.z * xv.z + w.w * xv.w;
            float4 u = rU[k], hv = h4[k];
            a += u.x * hv.x + u.y * hv.y + u.z * hv.z + u.w * hv.w;
        }
        acc[g] = warp_sum(a);
    }
    if (lane == 0) {
        float gi = acc[0] + b_ih[j]           + b_hh[j];
        float gf = acc[1] + b_ih[HID + j]     + b_hh[HID + j];
        float gg = acc[2] + b_ih[2 * HID + j] + b_hh[2 * HID + j];
        float go = acc[3] + b_ih[3 * HID + j] + b_hh[3 * HID + j];
        float ig = sigmoidf(gi);
        float fg = sigmoidf(gf);
        float gt = tanhf(gg);
        float og = sigmoidf(go);
        float cn = fg * c[j] + ig * gt;
        float hn = og * tanhf(cn);
        g_hnew[j] = hn;
        out_tail[j] = hn;          // h_new
        out_tail[HID + j] = cn;    // c_new
    }
}

// ---------------- K2: scores[t] = dot(A[t,:], h_new) ----------------
__global__ void k2_scores(const float* __restrict__ A) {
    __shared__ __align__(16) float sh[HID];
    for (int k = threadIdx.x; k < HID; k += blockDim.x) sh[k] = g_hnew[k];
    __syncthreads();

    int t = (blockIdx.x * blockDim.x + threadIdx.x) >> 5;
    int lane = threadIdx.x & 31;
    if (t >= MAXLEN) return;

    const float4* r = (const float4*)(A + (size_t)t * HID);
    const float4* h4 = (const float4*)sh;
    float a = 0.f;
#pragma unroll
    for (int k = lane; k < HID / 4; k += 32) {
        float4 v = r[k], hv = h4[k];
        a += v.x * hv.x + v.y * hv.y + v.z * hv.z + v.w * hv.w;
    }
    a = warp_sum(a);
    if (lane == 0) g_scores[t] = a;
}

// ---------------- K3: softmax stats (per block, redundant+deterministic) + ctx partials ----------------
// 128 blocks x 512 threads; block b handles timesteps [b*32, b*32+32)
__global__ void k3_ctx_part(const float* __restrict__ A) {
    __shared__ float red[32];   // per-warp partials (16 warps)
    __shared__ float w_s[32];
    int tid = threadIdx.x;
    int wid = tid >> 5, lane = tid & 31;

    // --- stats: each thread covers 8 scores (4096 / 512) ---
    float m = -INFINITY;
#pragma unroll
    for (int i = 0; i < 8; i++) m = fmaxf(m, g_scores[tid + i * 512]);
    m = warp_max(m);
    if (lane == 0) red[wid] = m;
    __syncthreads();
    if (wid == 0) {
        float v = (lane < 16) ? red[lane] : -INFINITY;
        v = warp_max(v);
        if (lane == 0) red[0] = v;
    }
    __syncthreads();
    m = red[0];
    __syncthreads();

    float l = 0.f;
#pragma unroll
    for (int i = 0; i < 8; i++) l += expf(g_scores[tid + i * 512] - m);
    l = warp_sum(l);
    if (lane == 0) red[wid] = l;
    __syncthreads();
    if (wid == 0) {
        float v = (lane < 16) ? red[lane] : 0.f;
        v = warp_sum(v);
        if (lane == 0) red[1] = 1.f / v;
    }
    __syncthreads();
    float inv_l = red[1];

    // --- weights for this block's 32 timesteps ---
    int t0 = blockIdx.x * 32;
    if (tid < 32) w_s[tid] = expf(g_scores[t0 + tid] - m) * inv_l;
    __syncthreads();

    // --- weighted accumulation (A rows are L2-resident after K2) ---
    float a0 = 0.f, a1 = 0.f;
#pragma unroll 8
    for (int t = 0; t < 32; t++) {
        const float* row = A + (size_t)(t0 + t) * HID;
        float w = w_s[t];
        a0 += row[tid] * w;
        a1 += row[tid + 512] * w;
    }
    g_ctx_part[blockIdx.x * HID + tid] = a0;
    g_ctx_part[blockIdx.x * HID + tid + 512] = a1;
}

// ---------------- K3b: reduce 128 partials -> ctx ----------------
// 8 blocks x 128 threads: block handles 128 consecutive d; coalesced per iter, unroll 8
__global__ void k3b_ctx_reduce() {
    int d = blockIdx.x * 128 + threadIdx.x;
    float s = 0.f;
#pragma unroll 8
    for (int b = 0; b < NPART; b++) s += g_ctx_part[b * HID + d];
    g_ctx[d] = s;
}

// ---------------- K4: fc1 GEMV ----------------
__global__ void k4_fc1(const float* __restrict__ fc1_w, const float* __restrict__ fc1_b) {
    __shared__ __align__(16) float sc[2 * HID];
    for (int k = threadIdx.x; k < HID; k += blockDim.x) {
        sc[k] = g_ctx[k];
        sc[HID + k] = g_hnew[k];
    }
    __syncthreads();

    int i = (blockIdx.x * blockDim.x + threadIdx.x) >> 5;
    int lane = threadIdx.x & 31;
    if (i >= HID) return;

    const float4* r = (const float4*)(fc1_w + (size_t)i * 2 * HID);
    const float4* c4 = (const float4*)sc;
    float a = 0.f;
#pragma unroll
    for (int k = lane; k < (2 * HID) / 4; k += 32) {
        float4 v = r[k], cv = c4[k];
        a += v.x * cv.x + v.y * cv.y + v.z * cv.z + v.w * cv.w;
    }
    a = warp_sum(a);
    if (lane == 0) g_hid[i] = a + fc1_b[i];
}

// ---------------- K5: fc2 GEMV -> logits ----------------
__global__ void k5_fc2(const float* __restrict__ fc2_w, const float* __restrict__ fc2_b,
                       float* __restrict__ out) {
    __shared__ __align__(16) float shd[HID];
    for (int k = threadIdx.x; k < HID; k += blockDim.x) shd[k] = g_hid[k];
    __syncthreads();

    int i = (blockIdx.x * blockDim.x + threadIdx.x) >> 5;
    if (i >= VOCAB) return;
    int lane = threadIdx.x & 31;

    const float4* r = (const float4*)(fc2_w + (size_t)i * HID);
    const float4* h4 = (const float4*)shd;
    float a = 0.f;
#pragma unroll
    for (int k = lane; k < HID / 4; k += 32) {
        float4 v = r[k], hv = h4[k];
        a += v.x * hv.x + v.y * hv.y + v.z * hv.z + v.w * hv.w;
    }
    a = warp_sum(a);
    if (lane == 0) out[i] = a + fc2_b[i];
}

// ---------------- K6: lse partials ----------------
__global__ void k6_lse_part(const float* __restrict__ out) {
    __shared__ float sm[256];
    __shared__ float sl[256];
    int idx = blockIdx.x * blockDim.x + threadIdx.x;
    float m = -INFINITY, l = 0.f;
    if (idx < VOCAB) { m = out[idx]; l = 1.f; }
    sm[threadIdx.x] = m;
    sl[threadIdx.x] = l;
    __syncthreads();
    for (int s = 128; s > 0; s >>= 1) {
        if (threadIdx.x < s) {
            float m1 = sm[threadIdx.x], l1 = sl[threadIdx.x];
            float m2 = sm[threadIdx.x + s], l2 = sl[threadIdx.x + s];
            float mm = fmaxf(m1, m2);
            float ll = (l1 > 0.f ? l1 * expf(m1 - mm) : 0.f) +
                       (l2 > 0.f ? l2 * expf(m2 - mm) : 0.f);
            sm[threadIdx.x] = mm;
            sl[threadIdx.x] = ll;
        }
        __syncthreads();
    }
    if (threadIdx.x == 0) {
        g_lse_m[blockIdx.x] = sm[0];
        g_lse_l[blockIdx.x] = sl[0];
    }
}

// ---------------- K7: combine + subtract in place ----------------
__global__ void k7_final(float* __restrict__ out) {
    __shared__ float sm[256];
    __shared__ float sl[256];
    int tid = threadIdx.x;
    sm[tid] = g_lse_m[tid];
    sl[tid] = g_lse_l[tid];
    __syncthreads();
    for (int s = 128; s > 0; s >>= 1) {
        if (tid < s) {
            float m1 = sm[tid], l1 = sl[tid];
            float m2 = sm[tid + s], l2 = sl[tid + s];
            float mm = fmaxf(m1, m2);
            float ll = (l1 > 0.f ? l1 * expf(m1 - mm) : 0.f) +
                       (l2 > 0.f ? l2 * expf(m2 - mm) : 0.f);
            sm[tid] = mm;
            sl[tid] = ll;
        }
        __syncthreads();
    }
    float lse = sm[0] + logf(sl[0]);
    int i = blockIdx.x * 256 + tid;
    if (i < VOCAB) out[i] -= lse;
}

// ---------------- launch ----------------
extern "C" void kernel_launch(void* const* d_in, const int* in_sizes, int n_in,
                              void* d_out, int out_size) {
    const float* attn  = (const float*)d_in[0];
    const float* x     = (const float*)d_in[1];
    const float* h     = (const float*)d_in[2];
    const float* c     = (const float*)d_in[3];
    const float* W_ih  = (const float*)d_in[4];
    const float* W_hh  = (const float*)d_in[5];
    const float* b_ih  = (const float*)d_in[6];
    const float* b_hh  = (const float*)d_in[7];
    const float* fc1_w = (const float*)d_in[8];
    const float* fc1_b = (const float*)d_in[9];
    const float* fc2_w = (const float*)d_in[10];
    const float* fc2_b = (const float*)d_in[11];
    float* out = (float*)d_out;

    k1_lstm<<<256, 128>>>(W_ih, W_hh, b_ih, b_hh, x, h, c, out + VOCAB);
    k2_scores<<<512, 256>>>(attn);
    k3_ctx_part<<<NPART, 512>>>(attn);
    k3b_ctx_reduce<<<8, 128>>>();
    k4_fc1<<<128, 256>>>(fc1_w, fc1_b);
    k5_fc2<<<(VOCAB + 7) / 8, 256>>>(fc2_w, fc2_b, out);
    k6_lse_part<<<256, 256>>>(out);
    k7_final<<<(VOCAB + 255) / 256, 256>>>(out);
}

// round 4
// speedup vs baseline: 1.1687x; 1.0742x over previous
#include <cuda_runtime.h>
#include <math.h>

#define HID 1024
#define EMB 1024
#define MAXLEN 4096
#define VOCAB 50257
#define NPART 128   // ctx partial blocks

// ---------------- device scratch ----------------
__device__ float g_hnew[HID];
__device__ float g_scores[MAXLEN];
__device__ float g_ctx_part[NPART * HID];
__device__ float g_ctx[HID];
__device__ float g_hid[HID];
__device__ float g_lse_m[256];
__device__ float g_lse_l[256];

__device__ __forceinline__ float warp_sum(float v) {
#pragma unroll
    for (int o = 16; o; o >>= 1) v += __shfl_down_sync(0xffffffffu, v, o);
    return v;
}
__device__ __forceinline__ float warp_max(float v) {
#pragma unroll
    for (int o = 16; o; o >>= 1) v = fmaxf(v, __shfl_down_sync(0xffffffffu, v, o));
    return v;
}

__device__ __forceinline__ float sigmoidf(float x) { return 1.f / (1.f + expf(-x)); }

// ---------------- K1: gates GEMV + LSTM pointwise ----------------
__global__ void k1_lstm(const float* __restrict__ W_ih, const float* __restrict__ W_hh,
                        const float* __restrict__ b_ih, const float* __restrict__ b_hh,
                        const float* __restrict__ x, const float* __restrict__ h,
                        const float* __restrict__ c, float* __restrict__ out_tail) {
    __shared__ __align__(16) float sx[EMB];
    __shared__ __align__(16) float sh[HID];
    for (int k = threadIdx.x; k < EMB; k += blockDim.x) sx[k] = x[k];
    for (int k = threadIdx.x; k < HID; k += blockDim.x) sh[k] = h[k];
    __syncthreads();

    int j = (blockIdx.x * blockDim.x + threadIdx.x) >> 5;
    int lane = threadIdx.x & 31;
    if (j >= HID) return;

    const float4* x4 = (const float4*)sx;
    const float4* h4 = (const float4*)sh;
    float acc[4];
#pragma unroll
    for (int g = 0; g < 4; g++) {
        const float4* rW = (const float4*)(W_ih + (size_t)(g * HID + j) * EMB);
        const float4* rU = (const float4*)(W_hh + (size_t)(g * HID + j) * HID);
        float a = 0.f;
#pragma unroll
        for (int k = lane; k < EMB / 4; k += 32) {
            float4 w = rW[k], xv = x4[k];
            a += w.x * xv.x + w.y * xv.y + w.z * xv.z + w.w * xv.w;
            float4 u = rU[k], hv = h4[k];
            a += u.x * hv.x + u.y * hv.y + u.z * hv.z + u.w * hv.w;
        }
        acc[g] = warp_sum(a);
    }
    if (lane == 0) {
        float gi = acc[0] + b_ih[j]           + b_hh[j];
        float gf = acc[1] + b_ih[HID + j]     + b_hh[HID + j];
        float gg = acc[2] + b_ih[2 * HID + j] + b_hh[2 * HID + j];
        float go = acc[3] + b_ih[3 * HID + j] + b_hh[3 * HID + j];
        float ig = sigmoidf(gi);
        float fg = sigmoidf(gf);
        float gt = tanhf(gg);
        float og = sigmoidf(go);
        float cn = fg * c[j] + ig * gt;
        float hn = og * tanhf(cn);
        g_hnew[j] = hn;
        out_tail[j] = hn;          // h_new
        out_tail[HID + j] = cn;    // c_new
    }
}

// ---------------- K2: scores[t] = dot(A[t,:], h_new) ----------------
__global__ void k2_scores(const float* __restrict__ A) {
    __shared__ __align__(16) float sh[HID];
    for (int k = threadIdx.x; k < HID; k += blockDim.x) sh[k] = g_hnew[k];
    __syncthreads();

    int t = (blockIdx.x * blockDim.x + threadIdx.x) >> 5;
    int lane = threadIdx.x & 31;
    if (t >= MAXLEN) return;

    const float4* r = (const float4*)(A + (size_t)t * HID);
    const float4* h4 = (const float4*)sh;
    float a = 0.f;
#pragma unroll
    for (int k = lane; k < HID / 4; k += 32) {
        float4 v = r[k], hv = h4[k];
        a += v.x * hv.x + v.y * hv.y + v.z * hv.z + v.w * hv.w;
    }
    a = warp_sum(a);
    if (lane == 0) g_scores[t] = a;
}

// ---------------- K3: softmax stats (per block, redundant+deterministic) + ctx partials ----------------
// 128 blocks x 512 threads; block b handles timesteps [b*32, b*32+32)
__global__ void k3_ctx_part(const float* __restrict__ A) {
    __shared__ float red[32];   // per-warp partials (16 warps)
    __shared__ float w_s[32];
    int tid = threadIdx.x;
    int wid = tid >> 5, lane = tid & 31;

    // --- stats: each thread covers 8 scores (4096 / 512) ---
    float m = -INFINITY;
#pragma unroll
    for (int i = 0; i < 8; i++) m = fmaxf(m, g_scores[tid + i * 512]);
    m = warp_max(m);
    if (lane == 0) red[wid] = m;
    __syncthreads();
    if (wid == 0) {
        float v = (lane < 16) ? red[lane] : -INFINITY;
        v = warp_max(v);
        if (lane == 0) red[0] = v;
    }
    __syncthreads();
    m = red[0];
    __syncthreads();

    float l = 0.f;
#pragma unroll
    for (int i = 0; i < 8; i++) l += expf(g_scores[tid + i * 512] - m);
    l = warp_sum(l);
    if (lane == 0) red[wid] = l;
    __syncthreads();
    if (wid == 0) {
        float v = (lane < 16) ? red[lane] : 0.f;
        v = warp_sum(v);
        if (lane == 0) red[1] = 1.f / v;
    }
    __syncthreads();
    float inv_l = red[1];

    // --- weights for this block's 32 timesteps ---
    int t0 = blockIdx.x * 32;
    if (tid < 32) w_s[tid] = expf(g_scores[t0 + tid] - m) * inv_l;
    __syncthreads();

    // --- weighted accumulation (A rows are L2-resident after K2) ---
    float a0 = 0.f, a1 = 0.f;
#pragma unroll 8
    for (int t = 0; t < 32; t++) {
        const float* row = A + (size_t)(t0 + t) * HID;
        float w = w_s[t];
        a0 += row[tid] * w;
        a1 += row[tid + 512] * w;
    }
    g_ctx_part[blockIdx.x * HID + tid] = a0;
    g_ctx_part[blockIdx.x * HID + tid + 512] = a1;
}

// ---------------- K3b: reduce 128 partials -> ctx (two-stage, high-MLP) ----------------
// 16 blocks x 512 threads. Block covers 64 d values.
// thread = (slice, d_local): slice in [0,8), d_local in [0,64).
// Each thread sums 16 partials (fully unrolled -> MLP=16, coalesced across d_local),
// then 8 slices combine through smem.
__global__ void k3b_ctx_reduce() {
    __shared__ float s[8][64];
    int d_local = threadIdx.x & 63;
    int slice   = threadIdx.x >> 6;      // 0..7
    int d = blockIdx.x * 64 + d_local;

    float acc = 0.f;
#pragma unroll
    for (int i = 0; i < 16; i++)
        acc += g_ctx_part[(slice * 16 + i) * HID + d];
    s[slice][d_local] = acc;
    __syncthreads();

    if (slice == 0) {
        float v = s[0][d_local];
#pragma unroll
        for (int k = 1; k < 8; k++) v += s[k][d_local];
        g_ctx[d] = v;
    }
}

// ---------------- K4: fc1 GEMV ----------------
__global__ void k4_fc1(const float* __restrict__ fc1_w, const float* __restrict__ fc1_b) {
    __shared__ __align__(16) float sc[2 * HID];
    for (int k = threadIdx.x; k < HID; k += blockDim.x) {
        sc[k] = g_ctx[k];
        sc[HID + k] = g_hnew[k];
    }
    __syncthreads();

    int i = (blockIdx.x * blockDim.x + threadIdx.x) >> 5;
    int lane = threadIdx.x & 31;
    if (i >= HID) return;

    const float4* r = (const float4*)(fc1_w + (size_t)i * 2 * HID);
    const float4* c4 = (const float4*)sc;
    float a = 0.f;
#pragma unroll
    for (int k = lane; k < (2 * HID) / 4; k += 32) {
        float4 v = r[k], cv = c4[k];
        a += v.x * cv.x + v.y * cv.y + v.z * cv.z + v.w * cv.w;
    }
    a = warp_sum(a);
    if (lane == 0) g_hid[i] = a + fc1_b[i];
}

// ---------------- K5: fc2 GEMV -> logits ----------------
__global__ void k5_fc2(const float* __restrict__ fc2_w, const float* __restrict__ fc2_b,
                       float* __restrict__ out) {
    __shared__ __align__(16) float shd[HID];
    for (int k = threadIdx.x; k < HID; k += blockDim.x) shd[k] = g_hid[k];
    __syncthreads();

    int i = (blockIdx.x * blockDim.x + threadIdx.x) >> 5;
    if (i >= VOCAB) return;
    int lane = threadIdx.x & 31;

    const float4* r = (const float4*)(fc2_w + (size_t)i * HID);
    const float4* h4 = (const float4*)shd;
    float a = 0.f;
#pragma unroll
    for (int k = lane; k < HID / 4; k += 32) {
        float4 v = r[k], hv = h4[k];
        a += v.x * hv.x + v.y * hv.y + v.z * hv.z + v.w * hv.w;
    }
    a = warp_sum(a);
    if (lane == 0) out[i] = a + fc2_b[i];
}

// ---------------- K6: lse partials ----------------
__global__ void k6_lse_part(const float* __restrict__ out) {
    __shared__ float sm[256];
    __shared__ float sl[256];
    int idx = blockIdx.x * blockDim.x + threadIdx.x;
    float m = -INFINITY, l = 0.f;
    if (idx < VOCAB) { m = out[idx]; l = 1.f; }
    sm[threadIdx.x] = m;
    sl[threadIdx.x] = l;
    __syncthreads();
    for (int s = 128; s > 0; s >>= 1) {
        if (threadIdx.x < s) {
            float m1 = sm[threadIdx.x], l1 = sl[threadIdx.x];
            float m2 = sm[threadIdx.x + s], l2 = sl[threadIdx.x + s];
            float mm = fmaxf(m1, m2);
            float ll = (l1 > 0.f ? l1 * expf(m1 - mm) : 0.f) +
                       (l2 > 0.f ? l2 * expf(m2 - mm) : 0.f);
            sm[threadIdx.x] = mm;
            sl[threadIdx.x] = ll;
        }
        __syncthreads();
    }
    if (threadIdx.x == 0) {
        g_lse_m[blockIdx.x] = sm[0];
        g_lse_l[blockIdx.x] = sl[0];
    }
}

// ---------------- K7: combine + subtract in place ----------------
__global__ void k7_final(float* __restrict__ out) {
    __shared__ float sm[256];
    __shared__ float sl[256];
    int tid = threadIdx.x;
    sm[tid] = g_lse_m[tid];
    sl[tid] = g_lse_l[tid];
    __syncthreads();
    for (int s = 128; s > 0; s >>= 1) {
        if (tid < s) {
            float m1 = sm[tid], l1 = sl[tid];
            float m2 = sm[tid + s], l2 = sl[tid + s];
            float mm = fmaxf(m1, m2);
            float ll = (l1 > 0.f ? l1 * expf(m1 - mm) : 0.f) +
                       (l2 > 0.f ? l2 * expf(m2 - mm) : 0.f);
            sm[tid] = mm;
            sl[tid] = ll;
        }
        __syncthreads();
    }
    float lse = sm[0] + logf(sl[0]);
    int i = blockIdx.x * 256 + tid;
    if (i < VOCAB) out[i] -= lse;
}

// ---------------- launch ----------------
extern "C" void kernel_launch(void* const* d_in, const int* in_sizes, int n_in,
                              void* d_out, int out_size) {
    const float* attn  = (const float*)d_in[0];
    const float* x     = (const float*)d_in[1];
    const float* h     = (const float*)d_in[2];
    const float* c     = (const float*)d_in[3];
    const float* W_ih  = (const float*)d_in[4];
    const float* W_hh  = (const float*)d_in[5];
    const float* b_ih  = (const float*)d_in[6];
    const float* b_hh  = (const float*)d_in[7];
    const float* fc1_w = (const float*)d_in[8];
    const float* fc1_b = (const float*)d_in[9];
    const float* fc2_w = (const float*)d_in[10];
    const float* fc2_b = (const float*)d_in[11];
    float* out = (float*)d_out;

    k1_lstm<<<256, 128>>>(W_ih, W_hh, b_ih, b_hh, x, h, c, out + VOCAB);
    k2_scores<<<512, 256>>>(attn);
    k3_ctx_part<<<NPART, 512>>>(attn);
    k3b_ctx_reduce<<<16, 512>>>();
    k4_fc1<<<128, 256>>>(fc1_w, fc1_b);
    k5_fc2<<<(VOCAB + 7) / 8, 256>>>(fc2_w, fc2_b, out);
    k6_lse_part<<<256, 256>>>(out);
    k7_final<<<(VOCAB + 255) / 256, 256>>>(out);
}